// round 1
// baseline (speedup 1.0000x reference)
#include <cuda_runtime.h>

// PatchIoULoss: reference's anchor loops run exactly once (B=16<64, C=1<64),
// so the computation is: for each batch b over the top-left 64x64 patch,
//   iand_b = sum(pred*target), ior_b = sum(pred)+sum(target)-iand_b
//   out = sum_b (1 - iand_b/ior_b)
// Inputs: pred (16,1,1024,1024) f32, target same. Output: scalar f32.

#define BATCH 16
#define WIMG  1024
#define WIN   64

__device__ float        g_partial[BATCH];
__device__ unsigned int g_count = 0;

__global__ void __launch_bounds__(256, 1)
patch_iou_kernel(const float* __restrict__ pred,
                 const float* __restrict__ target,
                 float* __restrict__ out)
{
    const int b   = blockIdx.x;
    const int tid = threadIdx.x;

    const float4* __restrict__ p =
        reinterpret_cast<const float4*>(pred   + (size_t)b * WIMG * WIMG);
    const float4* __restrict__ t =
        reinterpret_cast<const float4*>(target + (size_t)b * WIMG * WIMG);

    // Patch = rows 0..63, cols 0..63 => 16 float4 per row, row stride 256 float4.
    float iand = 0.0f, sp = 0.0f, st = 0.0f;

#pragma unroll
    for (int k = 0; k < 4; ++k) {
        const int f   = tid + k * 256;   // 0..1023 float4 index within patch
        const int row = f >> 4;          // f / 16
        const int c4  = f & 15;          // f % 16
        const float4 pv = p[row * (WIMG / 4) + c4];
        const float4 tv = t[row * (WIMG / 4) + c4];
        iand += pv.x * tv.x + pv.y * tv.y + pv.z * tv.z + pv.w * tv.w;
        sp   += pv.x + pv.y + pv.z + pv.w;
        st   += tv.x + tv.y + tv.z + tv.w;
    }

    // Warp reduction
#pragma unroll
    for (int o = 16; o > 0; o >>= 1) {
        iand += __shfl_down_sync(0xffffffffu, iand, o);
        sp   += __shfl_down_sync(0xffffffffu, sp,   o);
        st   += __shfl_down_sync(0xffffffffu, st,   o);
    }

    __shared__ float s_i[8], s_p[8], s_t[8];
    const int w = tid >> 5, l = tid & 31;
    if (l == 0) { s_i[w] = iand; s_p[w] = sp; s_t[w] = st; }
    __syncthreads();

    if (tid == 0) {
        float I = 0.0f, P = 0.0f, T = 0.0f;
#pragma unroll
        for (int i = 0; i < 8; ++i) { I += s_i[i]; P += s_p[i]; T += s_t[i]; }
        g_partial[b] = 1.0f - I / (P + T - I);
        __threadfence();
        const unsigned int ticket = atomicAdd(&g_count, 1u);
        if (ticket == BATCH - 1) {
            float s = 0.0f;
#pragma unroll
            for (int i = 0; i < BATCH; ++i) s += g_partial[i];
            *out = s;
            g_count = 0;   // reset for next (deterministic) replay
        }
    }
}

extern "C" void kernel_launch(void* const* d_in, const int* in_sizes, int n_in,
                              void* d_out, int out_size)
{
    const float* pred   = (const float*)d_in[0];
    const float* target = (const float*)d_in[1];
    float* out          = (float*)d_out;
    patch_iou_kernel<<<BATCH, 256>>>(pred, target, out);
}